// round 16
// baseline (speedup 1.0000x reference)
#include <cuda_runtime.h>

// DWT3D: fused separable Haar 3D analysis + octant->channel repack.
// x: (B=2, N=128, N, N, C=4) f32, A: (128,128) Haar analysis matrix.
// out: (B, 64, 64, 64, 32) f32, channel = octant*4 + c.
//
// Pipelined 2-tile kernel: grid 2048, block 256; block processes tile bid
// (n=0) and tile bid+2048 (n=1) -- identical (a,bb), fixed address offset.
// Double-buffered smem (2x16KB). Tile1's loads are issued right after the
// tile0 barrier, so their DRAM latency hides behind tile0's phase-2
// compute+stores. Halves exposed load latency per block; fewer waves.
//
// Access/policy (proven best): 32B .v4.b64 accesses, loads
// ld.global.nc.L2::evict_first, stores st.global.L2::evict_last.
//
// Octant/channel order (matching reference slicing, incl. HLH==HHH dup):
//   o0=lll o1=hll | o2=lhl o3=hhl | o4=llh o5=hhh | o6=lhh o7=hhh

#define NN 128
#define CC 4
#define HALF 64
#define LINES 2
#define XSTRIDE (NN * NN * NN * CC)          // +1 in n, input floats
#define OSTRIDE (HALF * HALF * HALF * 32)    // +1 in n, output floats

__device__ __forceinline__ void ldg_stream32(const float* p, float4& a, float4& b) {
    unsigned long long r0, r1, r2, r3;
    asm volatile("ld.global.nc.L2::evict_first.v4.b64 {%0,%1,%2,%3}, [%4];"
                 : "=l"(r0), "=l"(r1), "=l"(r2), "=l"(r3) : "l"(p));
    a.x = __uint_as_float((unsigned)r0);  a.y = __uint_as_float((unsigned)(r0 >> 32));
    a.z = __uint_as_float((unsigned)r1);  a.w = __uint_as_float((unsigned)(r1 >> 32));
    b.x = __uint_as_float((unsigned)r2);  b.y = __uint_as_float((unsigned)(r2 >> 32));
    b.z = __uint_as_float((unsigned)r3);  b.w = __uint_as_float((unsigned)(r3 >> 32));
}

__device__ __forceinline__ unsigned long long pk(float lo, float hi) {
    return (unsigned long long)__float_as_uint(lo)
         | ((unsigned long long)__float_as_uint(hi) << 32);
}

__device__ __forceinline__ void stg_pin32(float* p, float4 a, float4 b) {
    asm volatile("st.global.L2::evict_last.v4.b64 [%0], {%1,%2,%3,%4};"
                 :: "l"(p), "l"(pk(a.x, a.y)), "l"(pk(a.z, a.w)),
                    "l"(pk(b.x, b.y)), "l"(pk(b.z, b.w)) : "memory");
}

__device__ __forceinline__ float4 f4_comb(float s0, float4 a, float s1, float4 b) {
    float4 r;
    r.x = fmaf(s0, a.x, s1 * b.x);
    r.y = fmaf(s0, a.y, s1 * b.y);
    r.z = fmaf(s0, a.z, s1 * b.z);
    r.w = fmaf(s0, a.w, s1 * b.w);
    return r;
}

__global__ void __launch_bounds__(256) dwt3d_haar_pipe_kernel(
    const float* __restrict__ x,
    const float* __restrict__ A,
    float* __restrict__ out)
{
    // s[buf][line][kt][row][m]
    __shared__ float4 s[2][LINES][2][4][HALF];

    const int bid = blockIdx.x;          // 0..2047 -> tile0 (n=0), tile1 = +2048 (n=1)
    const int bb = bid & 31;             // b = 2*bb + l
    const int a  = (bid >> 5) & 63;
    const int tid = threadIdx.x;

    // Haar coefficients from the actual A matrix (no wrap for L=2).
    const float h00 = __ldg(&A[0]);
    const float h01 = __ldg(&A[1]);
    const float h10 = __ldg(&A[HALF * NN]);
    const float h11 = __ldg(&A[HALF * NN + 1]);

    // ---- Phase-1 thread mapping ----
    const int row = tid >> 6;            // 0..3 = si*2+sj
    const int m   = tid & 63;
    const int si  = row >> 1;
    const int sj  = row & 1;
    const float* g0 = x + ((si + 2 * a) * NN + (4 * bb + sj)) * NN * CC + 8 * m;  // n=0

    // ---- Phase-2 thread mapping ----
    const int pair = tid & 3;
    const int d = tid >> 2;
    const int kt = pair >> 1;
    const bool jAlo = !(pair & 1);
    const bool jBlo = (pair == 0);
    const float cja0 = jAlo ? h00 : h10, cja1 = jAlo ? h01 : h11;
    const float cjb0 = jBlo ? h00 : h10, cjb1 = jBlo ? h01 : h11;
    float* o0 = out + (((a * HALF + 2 * bb) * HALF + d) << 5) + 8 * pair;         // n=0

    // ---- Prologue: load tile0 ----
    float4 v0[LINES], v1[LINES];
#pragma unroll
    for (int l = 0; l < LINES; l++)
        ldg_stream32(g0 + 2 * l * NN * CC, v0[l], v1[l]);

    // ---- Iter 0: k-stage tile0 -> buf0 ----
#pragma unroll
    for (int l = 0; l < LINES; l++) {
        s[0][l][0][row][m] = f4_comb(h00, v0[l], h01, v1[l]);
        s[0][l][1][row][m] = f4_comb(h10, v0[l], h11, v1[l]);
    }
    __syncthreads();

    // ---- Prefetch tile1 (issue; latency hides behind phase2 of tile0) ----
    float4 w0[LINES], w1[LINES];
#pragma unroll
    for (int l = 0; l < LINES; l++)
        ldg_stream32(g0 + XSTRIDE + 2 * l * NN * CC, w0[l], w1[l]);

    // ---- Phase 2 tile0 ----
#pragma unroll
    for (int l = 0; l < LINES; l++) {
        float4 k00 = s[0][l][kt][0][d];
        float4 k01 = s[0][l][kt][1][d];
        float4 k10 = s[0][l][kt][2][d];
        float4 k11 = s[0][l][kt][3][d];
        float4 jA0 = f4_comb(cja0, k00, cja1, k01);
        float4 jA1 = f4_comb(cja0, k10, cja1, k11);
        float4 jB0 = f4_comb(cjb0, k00, cjb1, k01);
        float4 jB1 = f4_comb(cjb0, k10, cjb1, k11);
        stg_pin32(o0 + l * (HALF << 5),
                  f4_comb(h00, jA0, h01, jA1),
                  f4_comb(h10, jB0, h11, jB1));
    }

    // ---- Iter 1: k-stage tile1 -> buf1 ----
#pragma unroll
    for (int l = 0; l < LINES; l++) {
        s[1][l][0][row][m] = f4_comb(h00, w0[l], h01, w1[l]);
        s[1][l][1][row][m] = f4_comb(h10, w0[l], h11, w1[l]);
    }
    __syncthreads();

    // ---- Phase 2 tile1 ----
#pragma unroll
    for (int l = 0; l < LINES; l++) {
        float4 k00 = s[1][l][kt][0][d];
        float4 k01 = s[1][l][kt][1][d];
        float4 k10 = s[1][l][kt][2][d];
        float4 k11 = s[1][l][kt][3][d];
        float4 jA0 = f4_comb(cja0, k00, cja1, k01);
        float4 jA1 = f4_comb(cja0, k10, cja1, k11);
        float4 jB0 = f4_comb(cjb0, k00, cjb1, k01);
        float4 jB1 = f4_comb(cjb0, k10, cjb1, k11);
        stg_pin32(o0 + OSTRIDE + l * (HALF << 5),
                  f4_comb(h00, jA0, h01, jA1),
                  f4_comb(h10, jB0, h11, jB1));
    }
}

extern "C" void kernel_launch(void* const* d_in, const int* in_sizes, int n_in,
                              void* d_out, int out_size) {
    const float* x = (const float*)d_in[0];
    const float* A = (const float*)d_in[1];
    float* out = (float*)d_out;
    dwt3d_haar_pipe_kernel<<<2048, 256>>>(x, A, out);
}

// round 17
// speedup vs baseline: 1.0755x; 1.0755x over previous
#include <cuda_runtime.h>

// DWT3D: fused separable Haar 3D analysis + octant->channel repack.
// x: (B=2, N=128, N, N, C=4) f32, A: (128,128) Haar analysis matrix.
// out: (B, 64, 64, 64, 32) f32, channel = octant*4 + c.
//
// PERSISTENT version of the proven best kernel: grid = 1184 blocks
// (148 SMs x 8 resident blocks at 16KB smem / 32 regs); each block loops
// over tiles t = bid, bid+1184, ... < 4096. Eliminates wave transitions and
// the half-empty tail wave of the 4096-block launch. Tile body is identical:
//   Phase 1: 2 independent 32B LDGs per thread (MLP=2), k-stage, smem.
//   Phase 2: per line, j- and i-stage, one dense 32B store per line.
// Two barriers per tile (smem reuse hazard between phase2 and next phase1).
//
// Access/policy (proven best): 32B .v4.b64, loads L2::evict_first,
// stores L2::evict_last.
//
// Octant/channel order (matching reference slicing, incl. HLH==HHH dup):
//   o0=lll o1=hll | o2=lhl o3=hhl | o4=llh o5=hhh | o6=lhh o7=hhh

#define NN 128
#define CC 4
#define HALF 64
#define LINES 2
#define NTILES 4096
#define GRIDP 1184   // 148 SMs * 8 blocks

__device__ __forceinline__ void ldg_stream32(const float* p, float4& a, float4& b) {
    unsigned long long r0, r1, r2, r3;
    asm volatile("ld.global.nc.L2::evict_first.v4.b64 {%0,%1,%2,%3}, [%4];"
                 : "=l"(r0), "=l"(r1), "=l"(r2), "=l"(r3) : "l"(p));
    a.x = __uint_as_float((unsigned)r0);  a.y = __uint_as_float((unsigned)(r0 >> 32));
    a.z = __uint_as_float((unsigned)r1);  a.w = __uint_as_float((unsigned)(r1 >> 32));
    b.x = __uint_as_float((unsigned)r2);  b.y = __uint_as_float((unsigned)(r2 >> 32));
    b.z = __uint_as_float((unsigned)r3);  b.w = __uint_as_float((unsigned)(r3 >> 32));
}

__device__ __forceinline__ unsigned long long pk(float lo, float hi) {
    return (unsigned long long)__float_as_uint(lo)
         | ((unsigned long long)__float_as_uint(hi) << 32);
}

__device__ __forceinline__ void stg_pin32(float* p, float4 a, float4 b) {
    asm volatile("st.global.L2::evict_last.v4.b64 [%0], {%1,%2,%3,%4};"
                 :: "l"(p), "l"(pk(a.x, a.y)), "l"(pk(a.z, a.w)),
                    "l"(pk(b.x, b.y)), "l"(pk(b.z, b.w)) : "memory");
}

__device__ __forceinline__ float4 f4_comb(float s0, float4 a, float s1, float4 b) {
    float4 r;
    r.x = fmaf(s0, a.x, s1 * b.x);
    r.y = fmaf(s0, a.y, s1 * b.y);
    r.z = fmaf(s0, a.z, s1 * b.z);
    r.w = fmaf(s0, a.w, s1 * b.w);
    return r;
}

__global__ void __launch_bounds__(256) dwt3d_haar_pers_kernel(
    const float* __restrict__ x,
    const float* __restrict__ A,
    float* __restrict__ out)
{
    // s[line][kt][row][m]: kt 0=low,1=high (k-stage); row = si*2+sj
    __shared__ float4 s[LINES][2][4][HALF];

    const int tid = threadIdx.x;

    // Haar coefficients from the actual A matrix (no wrap for L=2).
    const float h00 = __ldg(&A[0]);
    const float h01 = __ldg(&A[1]);
    const float h10 = __ldg(&A[HALF * NN]);
    const float h11 = __ldg(&A[HALF * NN + 1]);

    // Phase-1 mapping (fixed across tiles)
    const int row = tid >> 6;      // 0..3 = si*2+sj
    const int m   = tid & 63;
    const int si  = row >> 1;
    const int sj  = row & 1;

    // Phase-2 mapping (fixed across tiles)
    const int pair = tid & 3;
    const int d = tid >> 2;
    const int kt = pair >> 1;
    const bool jAlo = !(pair & 1);
    const bool jBlo = (pair == 0);
    const float cja0 = jAlo ? h00 : h10, cja1 = jAlo ? h01 : h11;
    const float cjb0 = jBlo ? h00 : h10, cjb1 = jBlo ? h01 : h11;

    for (int t = blockIdx.x; t < NTILES; t += GRIDP) {
        const int bb = t & 31;            // b = 2*bb + l
        const int a  = (t >> 5) & 63;
        const int n  = t >> 11;

        // ---- Phase 1: 2x coalesced 32B loads (MLP=2) + k-stage ----
        {
            const int gi = 2 * a + si;
            const float* gbase = x + ((n * NN + gi) * NN + (4 * bb + sj)) * NN * CC + 8 * m;
            float4 v0[LINES], v1[LINES];
#pragma unroll
            for (int l = 0; l < LINES; l++)
                ldg_stream32(gbase + 2 * l * NN * CC, v0[l], v1[l]);
#pragma unroll
            for (int l = 0; l < LINES; l++) {
                s[l][0][row][m] = f4_comb(h00, v0[l], h01, v1[l]);  // k lowpass
                s[l][1][row][m] = f4_comb(h10, v0[l], h11, v1[l]);  // k highpass
            }
        }
        __syncthreads();

        // ---- Phase 2: j-stage + i-stage + dense 32B stores ----
        float* obase = out + ((((n * HALF + a) * HALF + 2 * bb) * HALF + d) << 5) + 8 * pair;
#pragma unroll
        for (int l = 0; l < LINES; l++) {
            float4 k00 = s[l][kt][0][d];
            float4 k01 = s[l][kt][1][d];
            float4 k10 = s[l][kt][2][d];
            float4 k11 = s[l][kt][3][d];

            float4 jA0 = f4_comb(cja0, k00, cja1, k01);
            float4 jA1 = f4_comb(cja0, k10, cja1, k11);
            float4 jB0 = f4_comb(cjb0, k00, cjb1, k01);
            float4 jB1 = f4_comb(cjb0, k10, cjb1, k11);

            float4 out0 = f4_comb(h00, jA0, h01, jA1);   // i lowpass
            float4 out1 = f4_comb(h10, jB0, h11, jB1);   // i highpass

            stg_pin32(obase + l * (HALF << 5), out0, out1);
        }
        __syncthreads();   // protect smem before next tile's phase 1
    }
}

extern "C" void kernel_launch(void* const* d_in, const int* in_sizes, int n_in,
                              void* d_out, int out_size) {
    const float* x = (const float*)d_in[0];
    const float* A = (const float*)d_in[1];
    float* out = (float*)d_out;
    dwt3d_haar_pers_kernel<<<GRIDP, 256>>>(x, A, out);
}